// round 12
// baseline (speedup 1.0000x reference)
#include <cuda_runtime.h>
#include <cuda_fp16.h>

// E=500000, P=4000000, D=U=64.
__device__ int g_counts[500032];      // per-dst neighbor count
__device__ int g_offsets[500032];     // exclusive prefix of counts
__device__ int g_cursor[500032];      // scatter cursors
__device__ int g_src_sorted[4000000]; // src ids grouped by dst
__device__ unsigned long long g_scanState[512]; // decoupled-lookback state
__device__ __half g_feat_h[500000 * 64];  // fp16 staged feature table (64 MB)

// f32x2 helpers (sm_103a packed fp32 pipe, PTX-only)
#define FMA2(d, a, b) \
    asm("fma.rn.f32x2 %0, %1, %2, %0;" : "+l"(d) : "l"(a), "l"(b))
#define PACK2(p, x) \
    asm("mov.b64 %0, {%1, %1};" : "=l"(p) : "f"(x))
#define UNPACK2(lo, hi, p) \
    asm("mov.b64 {%0, %1}, %2;" : "=f"(lo), "=f"(hi) : "l"(p))

// scan state flags (high 32 bits): 1 = aggregate, 2 = inclusive prefix
#define SCAN_AGG    1ULL
#define SCAN_PREFIX 2ULL

__device__ __forceinline__ void scan_publish(unsigned long long* p,
                                             unsigned long long flag, int val)
{
    unsigned long long v = (flag << 32) | (unsigned int)val;
    asm volatile("st.release.gpu.global.u64 [%0], %1;" :: "l"(p), "l"(v) : "memory");
}
__device__ __forceinline__ unsigned long long scan_peek(const unsigned long long* p)
{
    unsigned long long v;
    asm volatile("ld.acquire.gpu.global.u64 %0, [%1];" : "=l"(v) : "l"(p) : "memory");
    return v;
}

// ---------------------------------------------------------------------------
// Combined prep: blocks [0, nConv) stream-convert feat -> fp16; the rest
// histogram dst ids. nbr read with DEFAULT policy so the 32 MB pair list
// stays L2-resident for the scatter pass (feat read stays evict-first).
// ---------------------------------------------------------------------------
__global__ void prep_kernel(const float4* __restrict__ feat4, int n4, int nConv,
                            const int4* __restrict__ nbr2, int P2, int P)
{
    if ((int)blockIdx.x < nConv) {
        int i = blockIdx.x * 256 + threadIdx.x;
        if (i >= n4) return;
        float4 v = __ldcs(&feat4[i]);
        __half2 h0 = __floats2half2_rn(v.x, v.y);
        __half2 h1 = __floats2half2_rn(v.z, v.w);
        uint2 u;
        u.x = *reinterpret_cast<unsigned int*>(&h0);
        u.y = *reinterpret_cast<unsigned int*>(&h1);
        reinterpret_cast<uint2*>(g_feat_h)[i] = u;
    } else {
        int q = (blockIdx.x - nConv) * 256 + threadIdx.x;
        if (q >= P2) return;
        int4 e = nbr2[q];              // {dst0, src0, dst1, src1} - keep in L2
        atomicAdd(&g_counts[e.x], 1);
        int p1 = q * 2 + 1;
        if (p1 < P) atomicAdd(&g_counts[e.z], 1);
    }
}

// ---------------------------------------------------------------------------
// One-kernel exclusive scan of g_counts (chunks of 1024) with decoupled
// lookback. g_scanState must be zeroed before launch (memsetAsync).
// Writes g_offsets and g_cursor.
// ---------------------------------------------------------------------------
__global__ void scan_kernel(int E)
{
    __shared__ int s[256];
    __shared__ int sBase;

    const int tid  = threadIdx.x;
    const int bid  = blockIdx.x;
    const int base = bid * 1024 + tid * 4;

    int c[4];
    int tsum = 0;
    #pragma unroll
    for (int j = 0; j < 4; j++) {
        int idx = base + j;
        c[j] = (idx < E) ? g_counts[idx] : 0;
        tsum += c[j];
    }
    s[tid] = tsum;
    __syncthreads();
    // inclusive scan over thread sums
    for (int o = 1; o < 256; o <<= 1) {
        int t = (tid >= o) ? s[tid - o] : 0;
        __syncthreads();
        s[tid] += t;
        __syncthreads();
    }
    const int total = s[255];

    if (tid == 0) {
        if (bid == 0) {
            scan_publish(&g_scanState[0], SCAN_PREFIX, total);
            sBase = 0;
        } else {
            scan_publish(&g_scanState[bid], SCAN_AGG, total);
            int running = 0;
            int j = bid - 1;
            for (;;) {
                unsigned long long v = scan_peek(&g_scanState[j]);
                unsigned long long f = v >> 32;
                if (f == SCAN_PREFIX) { running += (int)(unsigned int)v; break; }
                if (f == SCAN_AGG)    { running += (int)(unsigned int)v; j--; continue; }
                // flag==0: predecessor not published yet -> spin
            }
            scan_publish(&g_scanState[bid], SCAN_PREFIX, running + total);
            sBase = running;
        }
    }
    __syncthreads();

    int run = sBase + (s[tid] - tsum);     // exclusive base for this thread
    #pragma unroll
    for (int j = 0; j < 4; j++) {
        int idx = base + j;
        if (idx < E) {
            g_offsets[idx] = run;
            g_cursor[idx]  = run;
        }
        run += c[j];
    }
}

// ---------------------------------------------------------------------------
__global__ void sort_scatter_kernel(const int4* __restrict__ nbr2, int P2, int P)
{
    int q = blockIdx.x * 256 + threadIdx.x;
    if (q >= P2) return;
    int4 e = nbr2[q];                      // L2-resident from prep
    int pos0 = atomicAdd(&g_cursor[e.x], 1);
    g_src_sorted[pos0] = e.y;
    int p1 = q * 2 + 1;
    if (p1 < P) {
        int pos1 = atomicAdd(&g_cursor[e.z], 1);
        g_src_sorted[pos1] = e.w;
    }
}

// ---------------------------------------------------------------------------
// Fused aggregate + GEMM (exact R9 structure — best measured).
// Phase 1 gather: half-warp team per dst row, fp16 table, padded MLP-8
// batches (lanes past the end clamp + predicate off; no serial tail).
// Phase 2: 64x64 f32x2 GEMM + bias.
// ---------------------------------------------------------------------------
__global__ void __launch_bounds__(256) agg_gemm_kernel(
    const float* __restrict__ W,      // [64, 64]
    const float* __restrict__ bias,   // [64]
    float* __restrict__ out,          // [E, 64]
    int E)
{
    __shared__ float sW[64 * 64];     // sW[k*64 + u]
    __shared__ float sA[64 * 66];     // sA[k*66 + r] (transposed, pad 66)

    const int tid  = threadIdx.x;
    const int row0 = blockIdx.x * 64;

    #pragma unroll
    for (int i = tid; i < 64 * 64; i += 256)
        sW[i] = W[i];

    // ---- Phase 1: gather + register accumulation -------------------------
    const int lane16 = tid & 15;          // column segment (4 halves = 8B)
    const int tteam  = tid >> 4;          // 0..15
    const uint2* __restrict__ fh =
        reinterpret_cast<const uint2*>(g_feat_h) + lane16;  // row stride 16

    #pragma unroll
    for (int rr = 0; rr < 4; rr++) {
        const int lr = rr * 16 + tteam;   // local row 0..63
        const int r  = row0 + lr;

        float a0 = 0.f, a1 = 0.f, a2 = 0.f, a3 = 0.f;
        if (r < E) {
            const int start = g_offsets[r];
            const int cnt   = g_counts[r];
            if (cnt > 0) {
                const int last  = start + cnt - 1;
                for (int i = start; i <= last; i += 8) {
                    int s_[8];
                    #pragma unroll
                    for (int j = 0; j < 8; j++) {
                        int idx = i + j;
                        s_[j] = __ldcs(&g_src_sorted[idx <= last ? idx : last]);
                    }
                    uint2 v[8];
                    #pragma unroll
                    for (int j = 0; j < 8; j++)
                        v[j] = fh[(long)s_[j] * 16];
                    #pragma unroll
                    for (int j = 0; j < 8; j++) {
                        if (i + j <= last) {
                            float2 f0 = __half22float2(*reinterpret_cast<__half2*>(&v[j].x));
                            float2 f1 = __half22float2(*reinterpret_cast<__half2*>(&v[j].y));
                            a0 += f0.x; a1 += f0.y; a2 += f1.x; a3 += f1.y;
                        }
                    }
                }
            }
        }
        sA[(lane16 * 4 + 0) * 66 + lr] = a0;
        sA[(lane16 * 4 + 1) * 66 + lr] = a1;
        sA[(lane16 * 4 + 2) * 66 + lr] = a2;
        sA[(lane16 * 4 + 3) * 66 + lr] = a3;
    }
    __syncthreads();

    // ---- Phase 2: 64x64 GEMM (f32x2), bias, store ------------------------
    const int rt = tid >> 4;
    const int ct = tid & 15;

    unsigned long long accq[2][4];
    #pragma unroll
    for (int rp = 0; rp < 2; rp++)
        #pragma unroll
        for (int j = 0; j < 4; j++)
            accq[rp][j] = 0ULL;

    #pragma unroll
    for (int k = 0; k < 64; k++) {
        const unsigned long long a01 =
            *reinterpret_cast<const unsigned long long*>(&sA[k * 66 + rt * 4]);
        const unsigned long long a23 =
            *reinterpret_cast<const unsigned long long*>(&sA[k * 66 + rt * 4 + 2]);
        const float4 w = *reinterpret_cast<const float4*>(&sW[k * 64 + ct * 4]);

        unsigned long long wx, wy, wz, ww;
        PACK2(wx, w.x); PACK2(wy, w.y); PACK2(wz, w.z); PACK2(ww, w.w);

        FMA2(accq[0][0], a01, wx); FMA2(accq[0][1], a01, wy);
        FMA2(accq[0][2], a01, wz); FMA2(accq[0][3], a01, ww);
        FMA2(accq[1][0], a23, wx); FMA2(accq[1][1], a23, wy);
        FMA2(accq[1][2], a23, wz); FMA2(accq[1][3], a23, ww);
    }

    float res[4][4];
    #pragma unroll
    for (int rp = 0; rp < 2; rp++)
        #pragma unroll
        for (int j = 0; j < 4; j++) {
            float lo, hi;
            UNPACK2(lo, hi, accq[rp][j]);
            res[rp * 2 + 0][j] = lo;
            res[rp * 2 + 1][j] = hi;
        }

    const float4 b = *reinterpret_cast<const float4*>(&bias[ct * 4]);

    #pragma unroll
    for (int i = 0; i < 4; i++) {
        int row = row0 + rt * 4 + i;
        if (row < E) {
            float4 v;
            v.x = res[i][0] + b.x;
            v.y = res[i][1] + b.y;
            v.z = res[i][2] + b.z;
            v.w = res[i][3] + b.w;
            *reinterpret_cast<float4*>(&out[row * 64 + ct * 4]) = v;
        }
    }
}

// ---------------------------------------------------------------------------
extern "C" void kernel_launch(void* const* d_in, const int* in_sizes, int n_in,
                              void* d_out, int out_size)
{
    const float* feat = (const float*)d_in[0];   // [E, 64] f32
    const int*   nbr  = (const int*)d_in[1];     // [P, 2]  i32
    const float* W    = (const float*)d_in[2];   // [64, 64] f32
    const float* bias = (const float*)d_in[3];   // [64] f32
    float* out = (float*)d_out;                  // [E, 64] f32

    const int E = in_sizes[0] / 64;
    const int P = in_sizes[1] / 2;

    const int P2    = (P + 1) / 2;
    const int blkP2 = (P2 + 255) / 256;
    const int NB    = (E + 1023) / 1024;         // <= 512 scan blocks
    const int n4    = E * 16;                    // float4 count for convert
    const int nConv = (n4 + 255) / 256;

    // zero counts + scan state via async memsets (graph-capturable, no alloc)
    void* counts_ptr = nullptr;
    cudaGetSymbolAddress(&counts_ptr, g_counts);
    cudaMemsetAsync(counts_ptr, 0, (size_t)E * sizeof(int), 0);
    void* state_ptr = nullptr;
    cudaGetSymbolAddress(&state_ptr, g_scanState);
    cudaMemsetAsync(state_ptr, 0, sizeof(unsigned long long) * 512, 0);

    prep_kernel<<<nConv + blkP2, 256>>>((const float4*)feat, n4, nConv,
                                        (const int4*)nbr, P2, P);   // #1
    scan_kernel<<<NB, 256>>>(E);                                    // #2
    sort_scatter_kernel<<<blkP2, 256>>>((const int4*)nbr, P2, P);   // #3

    const int blkA = (E + 63) / 64;
    agg_gemm_kernel<<<blkA, 256>>>(W, bias, out, E);                // #4
}

// round 14
// speedup vs baseline: 1.0588x; 1.0588x over previous
#include <cuda_runtime.h>
#include <cuda_fp16.h>

// E=500000, P=4000000, D=U=64.
__device__ int g_counts[500032];      // per-dst neighbor count
__device__ int g_offsets[500032];     // exclusive prefix of counts
__device__ int g_cursor[500032];      // scatter cursors
__device__ int g_src_sorted[4000000]; // src ids grouped by dst
__device__ int g_blockSums[512];
__device__ int g_blockOffs[512];
__device__ __half g_feat_h[500000 * 64];  // fp16 staged feature table (64 MB)

// f32x2 helpers (sm_103a packed fp32 pipe, PTX-only)
#define FMA2(d, a, b) \
    asm("fma.rn.f32x2 %0, %1, %2, %0;" : "+l"(d) : "l"(a), "l"(b))
#define PACK2(p, x) \
    asm("mov.b64 %0, {%1, %1};" : "=l"(p) : "f"(x))
#define UNPACK2(lo, hi, p) \
    asm("mov.b64 {%0, %1}, %2;" : "=f"(lo), "=f"(hi) : "l"(p))

// ---------------------------------------------------------------------------
// Combined prep: blocks [0, nConv) stream-convert feat -> fp16; the rest
// histogram dst ids. (R9 pipeline, verbatim.)
// ---------------------------------------------------------------------------
__global__ void prep_kernel(const float4* __restrict__ feat4, int n4, int nConv,
                            const int4* __restrict__ nbr2, int P2, int P)
{
    if ((int)blockIdx.x < nConv) {
        int i = blockIdx.x * 256 + threadIdx.x;
        if (i >= n4) return;
        float4 v = __ldcs(&feat4[i]);
        __half2 h0 = __floats2half2_rn(v.x, v.y);
        __half2 h1 = __floats2half2_rn(v.z, v.w);
        uint2 u;
        u.x = *reinterpret_cast<unsigned int*>(&h0);
        u.y = *reinterpret_cast<unsigned int*>(&h1);
        reinterpret_cast<uint2*>(g_feat_h)[i] = u;
    } else {
        int q = (blockIdx.x - nConv) * 256 + threadIdx.x;
        if (q >= P2) return;
        int4 e = __ldcs(&nbr2[q]);     // {dst0, src0, dst1, src1}
        atomicAdd(&g_counts[e.x], 1);
        int p1 = q * 2 + 1;
        if (p1 < P) atomicAdd(&g_counts[e.z], 1);
    }
}

// ---------------------------------------------------------------------------
__global__ void scan_partial_kernel(int E)
{
    __shared__ int s[256];
    const int tid  = threadIdx.x;
    const int base = blockIdx.x * 1024 + tid * 4;
    int t = 0;
    #pragma unroll
    for (int j = 0; j < 4; j++) {
        int idx = base + j;
        if (idx < E) t += g_counts[idx];
    }
    s[tid] = t;
    __syncthreads();
    for (int o = 128; o > 0; o >>= 1) {
        if (tid < o) s[tid] += s[tid + o];
        __syncthreads();
    }
    if (tid == 0) g_blockSums[blockIdx.x] = s[0];
}

__global__ void scan_blocksums_kernel(int NB)
{
    __shared__ int s[512];
    const int tid = threadIdx.x;
    int v = (tid < NB) ? g_blockSums[tid] : 0;
    s[tid] = v;
    __syncthreads();
    for (int o = 1; o < 512; o <<= 1) {
        int t = (tid >= o) ? s[tid - o] : 0;
        __syncthreads();
        s[tid] += t;
        __syncthreads();
    }
    if (tid < NB) g_blockOffs[tid] = s[tid] - v;
}

__global__ void scan_final_kernel(int E)
{
    __shared__ int s[256];
    const int tid  = threadIdx.x;
    const int base = blockIdx.x * 1024 + tid * 4;

    int c[4];
    int tsum = 0;
    #pragma unroll
    for (int j = 0; j < 4; j++) {
        int idx = base + j;
        c[j] = (idx < E) ? g_counts[idx] : 0;
        tsum += c[j];
    }
    s[tid] = tsum;
    __syncthreads();
    for (int o = 1; o < 256; o <<= 1) {
        int t = (tid >= o) ? s[tid - o] : 0;
        __syncthreads();
        s[tid] += t;
        __syncthreads();
    }
    int run = g_blockOffs[blockIdx.x] + (s[tid] - tsum);
    #pragma unroll
    for (int j = 0; j < 4; j++) {
        int idx = base + j;
        if (idx < E) {
            g_offsets[idx] = run;
            g_cursor[idx]  = run;
        }
        run += c[j];
    }
}

__global__ void sort_scatter_kernel(const int4* __restrict__ nbr2, int P2, int P)
{
    int q = blockIdx.x * 256 + threadIdx.x;
    if (q >= P2) return;
    int4 e = __ldcs(&nbr2[q]);
    int pos0 = atomicAdd(&g_cursor[e.x], 1);
    g_src_sorted[pos0] = e.y;
    int p1 = q * 2 + 1;
    if (p1 < P) {
        int pos1 = atomicAdd(&g_cursor[e.z], 1);
        g_src_sorted[pos1] = e.w;
    }
}

// ---------------------------------------------------------------------------
// Fused aggregate + GEMM.
// The block's index list (rows row0..row0+63 are CONTIGUOUS in g_src_sorted)
// is staged cooperatively into smem: 1 coalesced wavefront per 32 indices
// instead of 8 broadcast LDGs per batch, and the gather's idx->feat chain
// shortens from ~240 cyc (L2 LDG) to 29 cyc (LDS broadcast). Per-row
// fallback to the global path if a block exceeds IDX_CAP (mean 512, cap
// 2048 = +67 sigma).
// Phase 1 gather: half-warp team per dst row, fp16 table, padded MLP-8.
// Phase 2: 64x64 f32x2 GEMM + bias.
// ---------------------------------------------------------------------------
#define IDX_CAP 2048

__global__ void __launch_bounds__(256) agg_gemm_kernel(
    const float* __restrict__ W,      // [64, 64]
    const float* __restrict__ bias,   // [64]
    float* __restrict__ out,          // [E, 64]
    int E)
{
    __shared__ float sW[64 * 64];     // sW[k*64 + u]
    __shared__ float sA[64 * 66];     // sA[k*66 + r] (transposed, pad 66)
    __shared__ int   sIdx[IDX_CAP];   // staged index list for this block

    const int tid  = threadIdx.x;
    const int row0 = blockIdx.x * 64;

    #pragma unroll
    for (int i = tid; i < 64 * 64; i += 256)
        sW[i] = W[i];

    // Block's contiguous index range in g_src_sorted.
    const int rowEndId = min(row0 + 64, E) - 1;            // last valid row
    const int blockStart = g_offsets[row0];
    const int nTotal = g_offsets[rowEndId] + g_counts[rowEndId] - blockStart;
    const int nStage = nTotal < IDX_CAP ? nTotal : IDX_CAP;
    for (int i = tid; i < nStage; i += 256)
        sIdx[i] = __ldcs(&g_src_sorted[blockStart + i]);
    __syncthreads();

    // ---- Phase 1: gather + register accumulation -------------------------
    const int lane16 = tid & 15;          // column segment (4 halves = 8B)
    const int tteam  = tid >> 4;          // 0..15
    const uint2* __restrict__ fh =
        reinterpret_cast<const uint2*>(g_feat_h) + lane16;  // row stride 16

    #pragma unroll
    for (int rr = 0; rr < 4; rr++) {
        const int lr = rr * 16 + tteam;   // local row 0..63
        const int r  = row0 + lr;

        float a0 = 0.f, a1 = 0.f, a2 = 0.f, a3 = 0.f;
        if (r < E) {
            const int start = g_offsets[r];
            const int cnt   = g_counts[r];
            if (cnt > 0) {
                const int sl   = start - blockStart;      // local start
                const int lastl = sl + cnt - 1;           // local last
                if (lastl < IDX_CAP) {
                    // Fast path: indices from smem (broadcast LDS, 29 cyc).
                    for (int i = sl; i <= lastl; i += 8) {
                        int s_[8];
                        #pragma unroll
                        for (int j = 0; j < 8; j++) {
                            int idx = i + j;
                            s_[j] = sIdx[idx <= lastl ? idx : lastl];
                        }
                        uint2 v[8];
                        #pragma unroll
                        for (int j = 0; j < 8; j++)
                            v[j] = fh[(long)s_[j] * 16];
                        #pragma unroll
                        for (int j = 0; j < 8; j++) {
                            if (i + j <= lastl) {
                                float2 f0 = __half22float2(*reinterpret_cast<__half2*>(&v[j].x));
                                float2 f1 = __half22float2(*reinterpret_cast<__half2*>(&v[j].y));
                                a0 += f0.x; a1 += f0.y; a2 += f1.x; a3 += f1.y;
                            }
                        }
                    }
                } else {
                    // Overflow fallback (astronomically rare): global path.
                    const int last = start + cnt - 1;
                    for (int i = start; i <= last; i += 8) {
                        int s_[8];
                        #pragma unroll
                        for (int j = 0; j < 8; j++) {
                            int idx = i + j;
                            s_[j] = __ldcs(&g_src_sorted[idx <= last ? idx : last]);
                        }
                        uint2 v[8];
                        #pragma unroll
                        for (int j = 0; j < 8; j++)
                            v[j] = fh[(long)s_[j] * 16];
                        #pragma unroll
                        for (int j = 0; j < 8; j++) {
                            if (i + j <= last) {
                                float2 f0 = __half22float2(*reinterpret_cast<__half2*>(&v[j].x));
                                float2 f1 = __half22float2(*reinterpret_cast<__half2*>(&v[j].y));
                                a0 += f0.x; a1 += f0.y; a2 += f1.x; a3 += f1.y;
                            }
                        }
                    }
                }
            }
        }
        sA[(lane16 * 4 + 0) * 66 + lr] = a0;
        sA[(lane16 * 4 + 1) * 66 + lr] = a1;
        sA[(lane16 * 4 + 2) * 66 + lr] = a2;
        sA[(lane16 * 4 + 3) * 66 + lr] = a3;
    }
    __syncthreads();

    // ---- Phase 2: 64x64 GEMM (f32x2), bias, store ------------------------
    const int rt = tid >> 4;
    const int ct = tid & 15;

    unsigned long long accq[2][4];
    #pragma unroll
    for (int rp = 0; rp < 2; rp++)
        #pragma unroll
        for (int j = 0; j < 4; j++)
            accq[rp][j] = 0ULL;

    #pragma unroll
    for (int k = 0; k < 64; k++) {
        const unsigned long long a01 =
            *reinterpret_cast<const unsigned long long*>(&sA[k * 66 + rt * 4]);
        const unsigned long long a23 =
            *reinterpret_cast<const unsigned long long*>(&sA[k * 66 + rt * 4 + 2]);
        const float4 w = *reinterpret_cast<const float4*>(&sW[k * 64 + ct * 4]);

        unsigned long long wx, wy, wz, ww;
        PACK2(wx, w.x); PACK2(wy, w.y); PACK2(wz, w.z); PACK2(ww, w.w);

        FMA2(accq[0][0], a01, wx); FMA2(accq[0][1], a01, wy);
        FMA2(accq[0][2], a01, wz); FMA2(accq[0][3], a01, ww);
        FMA2(accq[1][0], a23, wx); FMA2(accq[1][1], a23, wy);
        FMA2(accq[1][2], a23, wz); FMA2(accq[1][3], a23, ww);
    }

    float res[4][4];
    #pragma unroll
    for (int rp = 0; rp < 2; rp++)
        #pragma unroll
        for (int j = 0; j < 4; j++) {
            float lo, hi;
            UNPACK2(lo, hi, accq[rp][j]);
            res[rp * 2 + 0][j] = lo;
            res[rp * 2 + 1][j] = hi;
        }

    const float4 b = *reinterpret_cast<const float4*>(&bias[ct * 4]);

    #pragma unroll
    for (int i = 0; i < 4; i++) {
        int row = row0 + rt * 4 + i;
        if (row < E) {
            float4 v;
            v.x = res[i][0] + b.x;
            v.y = res[i][1] + b.y;
            v.z = res[i][2] + b.z;
            v.w = res[i][3] + b.w;
            *reinterpret_cast<float4*>(&out[row * 64 + ct * 4]) = v;
        }
    }
}

// ---------------------------------------------------------------------------
extern "C" void kernel_launch(void* const* d_in, const int* in_sizes, int n_in,
                              void* d_out, int out_size)
{
    const float* feat = (const float*)d_in[0];   // [E, 64] f32
    const int*   nbr  = (const int*)d_in[1];     // [P, 2]  i32
    const float* W    = (const float*)d_in[2];   // [64, 64] f32
    const float* bias = (const float*)d_in[3];   // [64] f32
    float* out = (float*)d_out;                  // [E, 64] f32

    const int E = in_sizes[0] / 64;
    const int P = in_sizes[1] / 2;

    const int P2    = (P + 1) / 2;
    const int blkP2 = (P2 + 255) / 256;
    const int NB    = (E + 1023) / 1024;         // <= 512
    const int n4    = E * 16;                    // float4 count for convert
    const int nConv = (n4 + 255) / 256;

    // zero counts via async memset (graph-capturable, no alloc)
    void* counts_ptr = nullptr;
    cudaGetSymbolAddress(&counts_ptr, g_counts);
    cudaMemsetAsync(counts_ptr, 0, (size_t)E * sizeof(int), 0);

    prep_kernel<<<nConv + blkP2, 256>>>((const float4*)feat, n4, nConv,
                                        (const int4*)nbr, P2, P);
    scan_partial_kernel<<<NB, 256>>>(E);
    scan_blocksums_kernel<<<1, 512>>>(NB);
    scan_final_kernel<<<NB, 256>>>(E);
    sort_scatter_kernel<<<blkP2, 256>>>((const int4*)nbr, P2, P);

    const int blkA = (E + 63) / 64;
    agg_gemm_kernel<<<blkA, 256>>>(W, bias, out, E);
}

// round 15
// speedup vs baseline: 1.1034x; 1.0421x over previous
#include <cuda_runtime.h>
#include <cuda_fp16.h>

// E=500000, P=4000000, D=U=64.
__device__ int g_counts[500032];      // per-dst neighbor count
__device__ int g_offsets[500032];     // exclusive prefix of counts
__device__ int g_cursor[500032];      // scatter cursors
__device__ int g_src_sorted[4000000]; // src ids grouped by dst
__device__ int g_blockSums[512];
__device__ int g_blockOffs[512];
__device__ __half g_xform_h[500000 * 64]; // fp16 transformed features (feat@W)

// ---------------------------------------------------------------------------
// prep: blocks [0, nXf) compute xform = fp16(feat @ W) with HMMA
// (mma.sync.m16n8k16); remaining blocks histogram dst ids.
// Per xform block: 8 warps x 16 rows = 128 feat rows. A fragments are built
// by loading feat fp32 directly in fragment layout and converting; B (W) is
// staged once per block in smem as packed half2 pairs [n][k2] (stride 36
// words -> conflict-free b-frag fetch).
// ---------------------------------------------------------------------------
__global__ void prep_kernel(const float* __restrict__ feat,
                            const float* __restrict__ W,
                            int nXf, int E,
                            const int4* __restrict__ nbr2, int P2, int P)
{
    __shared__ __half2 sWb[64 * 36];   // [n][k2]: (W[2k2][n], W[2k2+1][n])

    if ((int)blockIdx.x < nXf) {
        // Stage W packed along k.
        for (int i = threadIdx.x; i < 64 * 32; i += 256) {
            int n  = i >> 5;
            int k2 = i & 31;
            sWb[n * 36 + k2] = __floats2half2_rn(W[(2 * k2)     * 64 + n],
                                                 W[(2 * k2 + 1) * 64 + n]);
        }
        __syncthreads();

        const int warp = threadIdx.x >> 5;
        const int lane = threadIdx.x & 31;
        const int m0   = blockIdx.x * 128 + warp * 16;
        const int r    = lane >> 2;          // 0..7
        const int c2   = (lane & 3) * 2;     // 0,2,4,6
        const int rowLo = m0 + r;
        const int rowHi = m0 + r + 8;

        // A fragments for all 4 k-steps (a0:lo/k0-7 a1:hi/k0-7 a2:lo/k8-15 a3:hi/k8-15)
        unsigned int afr[4][4];
        #pragma unroll
        for (int ks = 0; ks < 4; ks++) {
            const int k0 = ks * 16;
            float2 lo0 = make_float2(0.f, 0.f), hi0 = lo0, lo8 = lo0, hi8 = lo0;
            if (rowLo < E) {
                lo0 = *reinterpret_cast<const float2*>(&feat[(long)rowLo * 64 + k0 + c2]);
                lo8 = *reinterpret_cast<const float2*>(&feat[(long)rowLo * 64 + k0 + 8 + c2]);
            }
            if (rowHi < E) {
                hi0 = *reinterpret_cast<const float2*>(&feat[(long)rowHi * 64 + k0 + c2]);
                hi8 = *reinterpret_cast<const float2*>(&feat[(long)rowHi * 64 + k0 + 8 + c2]);
            }
            __half2 h;
            h = __floats2half2_rn(lo0.x, lo0.y); afr[ks][0] = *reinterpret_cast<unsigned int*>(&h);
            h = __floats2half2_rn(hi0.x, hi0.y); afr[ks][1] = *reinterpret_cast<unsigned int*>(&h);
            h = __floats2half2_rn(lo8.x, lo8.y); afr[ks][2] = *reinterpret_cast<unsigned int*>(&h);
            h = __floats2half2_rn(hi8.x, hi8.y); afr[ks][3] = *reinterpret_cast<unsigned int*>(&h);
        }

        const int bn = lane >> 2;            // B col within n8 tile
        const int bk = lane & 3;             // B k2 sub-index

        #pragma unroll
        for (int nt = 0; nt < 8; nt++) {
            const int n0 = nt * 8;
            float d0 = 0.f, d1 = 0.f, d2 = 0.f, d3 = 0.f;
            #pragma unroll
            for (int ks = 0; ks < 4; ks++) {
                const int koff2 = ks * 8;
                const __half2 hb0 = sWb[(n0 + bn) * 36 + koff2 + bk];
                const __half2 hb1 = sWb[(n0 + bn) * 36 + koff2 + 4 + bk];
                const unsigned int b0 = *reinterpret_cast<const unsigned int*>(&hb0);
                const unsigned int b1 = *reinterpret_cast<const unsigned int*>(&hb1);
                asm volatile(
                    "mma.sync.aligned.m16n8k16.row.col.f32.f16.f16.f32 "
                    "{%0,%1,%2,%3}, {%4,%5,%6,%7}, {%8,%9}, {%0,%1,%2,%3};"
                    : "+f"(d0), "+f"(d1), "+f"(d2), "+f"(d3)
                    : "r"(afr[ks][0]), "r"(afr[ks][1]),
                      "r"(afr[ks][2]), "r"(afr[ks][3]),
                      "r"(b0), "r"(b1));
            }
            if (rowLo < E)
                *reinterpret_cast<__half2*>(&g_xform_h[(long)rowLo * 64 + n0 + c2]) =
                    __floats2half2_rn(d0, d1);
            if (rowHi < E)
                *reinterpret_cast<__half2*>(&g_xform_h[(long)rowHi * 64 + n0 + c2]) =
                    __floats2half2_rn(d2, d3);
        }
    } else {
        int q = (blockIdx.x - nXf) * 256 + threadIdx.x;
        if (q >= P2) return;
        int4 e = __ldcs(&nbr2[q]);     // {dst0, src0, dst1, src1}
        atomicAdd(&g_counts[e.x], 1);
        int p1 = q * 2 + 1;
        if (p1 < P) atomicAdd(&g_counts[e.z], 1);
    }
}

// ---------------------------------------------------------------------------
__global__ void scan_partial_kernel(int E)
{
    __shared__ int s[256];
    const int tid  = threadIdx.x;
    const int base = blockIdx.x * 1024 + tid * 4;
    int t = 0;
    #pragma unroll
    for (int j = 0; j < 4; j++) {
        int idx = base + j;
        if (idx < E) t += g_counts[idx];
    }
    s[tid] = t;
    __syncthreads();
    for (int o = 128; o > 0; o >>= 1) {
        if (tid < o) s[tid] += s[tid + o];
        __syncthreads();
    }
    if (tid == 0) g_blockSums[blockIdx.x] = s[0];
}

__global__ void scan_blocksums_kernel(int NB)
{
    __shared__ int s[512];
    const int tid = threadIdx.x;
    int v = (tid < NB) ? g_blockSums[tid] : 0;
    s[tid] = v;
    __syncthreads();
    for (int o = 1; o < 512; o <<= 1) {
        int t = (tid >= o) ? s[tid - o] : 0;
        __syncthreads();
        s[tid] += t;
        __syncthreads();
    }
    if (tid < NB) g_blockOffs[tid] = s[tid] - v;
}

__global__ void scan_final_kernel(int E)
{
    __shared__ int s[256];
    const int tid  = threadIdx.x;
    const int base = blockIdx.x * 1024 + tid * 4;

    int c[4];
    int tsum = 0;
    #pragma unroll
    for (int j = 0; j < 4; j++) {
        int idx = base + j;
        c[j] = (idx < E) ? g_counts[idx] : 0;
        tsum += c[j];
    }
    s[tid] = tsum;
    __syncthreads();
    for (int o = 1; o < 256; o <<= 1) {
        int t = (tid >= o) ? s[tid - o] : 0;
        __syncthreads();
        s[tid] += t;
        __syncthreads();
    }
    int run = g_blockOffs[blockIdx.x] + (s[tid] - tsum);
    #pragma unroll
    for (int j = 0; j < 4; j++) {
        int idx = base + j;
        if (idx < E) {
            g_offsets[idx] = run;
            g_cursor[idx]  = run;
        }
        run += c[j];
    }
}

__global__ void sort_scatter_kernel(const int4* __restrict__ nbr2, int P2, int P)
{
    int q = blockIdx.x * 256 + threadIdx.x;
    if (q >= P2) return;
    int4 e = __ldcs(&nbr2[q]);
    int pos0 = atomicAdd(&g_cursor[e.x], 1);
    g_src_sorted[pos0] = e.y;
    int p1 = q * 2 + 1;
    if (p1 < P) {
        int pos1 = atomicAdd(&g_cursor[e.z], 1);
        g_src_sorted[pos1] = e.w;
    }
}

// ---------------------------------------------------------------------------
// Aggregate kernel: out[r,:] = sum_{s in nbrs(r)} xform[s,:] + bias.
// The GEMM already happened in prep, so this is a pure gather+sum: half-warp
// team per dst row, padded MLP-8 batches (R9's proven loop), fp32 accum,
// direct float4 store. NO shared memory, NO __syncthreads, no straggler
// barrier — each team finishes its rows and exits.
// ---------------------------------------------------------------------------
__global__ void __launch_bounds__(256) agg_kernel(
    const float* __restrict__ bias,   // [64]
    float* __restrict__ out,          // [E, 64]
    int E)
{
    const int tid  = threadIdx.x;
    const int row0 = blockIdx.x * 64;
    const int lane16 = tid & 15;          // column segment (4 halves = 8B)
    const int tteam  = tid >> 4;          // 0..15
    const uint2* __restrict__ fh =
        reinterpret_cast<const uint2*>(g_xform_h) + lane16;  // row stride 16
    const float4 b = *reinterpret_cast<const float4*>(&bias[lane16 * 4]);

    #pragma unroll
    for (int rr = 0; rr < 4; rr++) {
        const int lr = rr * 16 + tteam;   // local row 0..63
        const int r  = row0 + lr;
        if (r >= E) continue;

        float a0 = 0.f, a1 = 0.f, a2 = 0.f, a3 = 0.f;
        const int start = g_offsets[r];
        const int cnt   = g_counts[r];
        if (cnt > 0) {
            const int last = start + cnt - 1;
            for (int i = start; i <= last; i += 8) {
                int s_[8];
                #pragma unroll
                for (int j = 0; j < 8; j++) {
                    int idx = i + j;
                    s_[j] = __ldcs(&g_src_sorted[idx <= last ? idx : last]);
                }
                uint2 v[8];
                #pragma unroll
                for (int j = 0; j < 8; j++)
                    v[j] = fh[(long)s_[j] * 16];
                #pragma unroll
                for (int j = 0; j < 8; j++) {
                    if (i + j <= last) {
                        float2 f0 = __half22float2(*reinterpret_cast<__half2*>(&v[j].x));
                        float2 f1 = __half22float2(*reinterpret_cast<__half2*>(&v[j].y));
                        a0 += f0.x; a1 += f0.y; a2 += f1.x; a3 += f1.y;
                    }
                }
            }
        }
        float4 o;
        o.x = a0 + b.x; o.y = a1 + b.y; o.z = a2 + b.z; o.w = a3 + b.w;
        *reinterpret_cast<float4*>(&out[(long)r * 64 + lane16 * 4]) = o;
    }
}

// ---------------------------------------------------------------------------
extern "C" void kernel_launch(void* const* d_in, const int* in_sizes, int n_in,
                              void* d_out, int out_size)
{
    const float* feat = (const float*)d_in[0];   // [E, 64] f32
    const int*   nbr  = (const int*)d_in[1];     // [P, 2]  i32
    const float* W    = (const float*)d_in[2];   // [64, 64] f32
    const float* bias = (const float*)d_in[3];   // [64] f32
    float* out = (float*)d_out;                  // [E, 64] f32

    const int E = in_sizes[0] / 64;
    const int P = in_sizes[1] / 2;

    const int P2    = (P + 1) / 2;
    const int blkP2 = (P2 + 255) / 256;
    const int NB    = (E + 1023) / 1024;         // <= 512
    const int nXf   = (E + 127) / 128;           // HMMA transform blocks

    // zero counts via async memset (graph-capturable, no alloc)
    void* counts_ptr = nullptr;
    cudaGetSymbolAddress(&counts_ptr, g_counts);
    cudaMemsetAsync(counts_ptr, 0, (size_t)E * sizeof(int), 0);

    prep_kernel<<<nXf + blkP2, 256>>>(feat, W, nXf, E,
                                      (const int4*)nbr, P2, P);   // #1
    scan_partial_kernel<<<NB, 256>>>(E);                          // #2
    scan_blocksums_kernel<<<1, 512>>>(NB);                        // #3
    scan_final_kernel<<<NB, 256>>>(E);                            // #4
    sort_scatter_kernel<<<blkP2, 256>>>((const int4*)nbr, P2, P); // #5

    const int blkA = (E + 63) / 64;
    agg_kernel<<<blkA, 256>>>(bias, out, E);                      // #6
}